// round 1
// baseline (speedup 1.0000x reference)
#include <cuda_runtime.h>
#include <cstdint>

typedef unsigned long long ull;

// Problem constants
constexpr int T_TOK   = 16384;     // 4 * 4096 tokens
constexpr int H_DIM   = 4096;
constexpr int N_E     = 64;        // experts
constexpr int B_BATCH = 4;
constexpr int S_SEQ   = 4096;
constexpr int TOPK    = 6;

// GEMM tiling
constexpr int KSPLIT = 4;
constexpr int HSL    = H_DIM / KSPLIT;  // 1024 per k-slice
constexpr int BM     = 128;             // tokens per block
constexpr int BK     = 16;

// Scratch (static device memory; no allocations allowed)
__device__ float g_part[KSPLIT][T_TOK][N_E];   // 16 MB split-K partials
__device__ float g_ssum[B_BATCH][N_E];         // sum of softmax scores per (b,e)
__device__ float g_cnt [B_BATCH][N_E];         // top-k selection counts per (b,e)

__global__ void zero_kernel() {
    int i = threadIdx.x;
    if (i < B_BATCH * N_E) {
        ((float*)g_ssum)[i] = 0.f;
        ((float*)g_cnt )[i] = 0.f;
    }
}

// ---------------------------------------------------------------------------
// GEMM: logits[t][e] = sum_h X[t][h] * W[e][h], split over KSPLIT h-slices.
// 128 threads, each computes an 8-token x 8-expert register tile using
// packed f32x2 FFMA (2 experts per accumulator register).
// ---------------------------------------------------------------------------
__global__ __launch_bounds__(128) void gemm_kernel(const float* __restrict__ X,
                                                   const float* __restrict__ W) {
    __shared__ float Xs[BK][BM + 4];    // k-major, padded (stride 132 floats, 16B aligned)
    __shared__ float Ws[BK][N_E + 4];   // k-major, padded (stride 68 floats, 16B aligned)

    const int tid = threadIdx.x;
    const int mb  = blockIdx.x;
    const int ks  = blockIdx.y;
    const int tx  = tid & 7;    // expert group: experts [tx*8, tx*8+8)
    const int ty  = tid >> 3;   // token group:  tokens  [ty*8, ty*8+8)
    const int t0  = mb * BM;
    const int h0  = ks * HSL;

    ull acc[8][4];              // [token][expert-pair], f32x2 packed
    #pragma unroll
    for (int i = 0; i < 8; i++)
        #pragma unroll
        for (int j = 0; j < 4; j++) acc[i][j] = 0ULL;

    const int lr = tid >> 2;        // 0..31 row within load pass
    const int lc = (tid & 3) * 4;   // 0,4,8,12 column (float4)

    for (int hk = 0; hk < HSL; hk += BK) {
        // Stage X tile (128 tokens x 16 k), transposed into k-major smem
        #pragma unroll
        for (int p = 0; p < 4; p++) {
            int row = p * 32 + lr;
            float4 v = *(const float4*)(X + (size_t)(t0 + row) * H_DIM + (h0 + hk + lc));
            Xs[lc + 0][row] = v.x; Xs[lc + 1][row] = v.y;
            Xs[lc + 2][row] = v.z; Xs[lc + 3][row] = v.w;
        }
        // Stage W tile (64 experts x 16 k), transposed into k-major smem
        #pragma unroll
        for (int p = 0; p < 2; p++) {
            int row = p * 32 + lr;
            float4 v = *(const float4*)(W + (size_t)row * H_DIM + (h0 + hk + lc));
            Ws[lc + 0][row] = v.x; Ws[lc + 1][row] = v.y;
            Ws[lc + 2][row] = v.z; Ws[lc + 3][row] = v.w;
        }
        __syncthreads();

        #pragma unroll
        for (int k = 0; k < BK; k++) {
            float4 xa = *(const float4*)&Xs[k][ty * 8];
            float4 xb = *(const float4*)&Xs[k][ty * 8 + 4];
            ulonglong2 wa = *(const ulonglong2*)&Ws[k][tx * 8];      // experts 0..3 (2 pairs)
            ulonglong2 wb = *(const ulonglong2*)&Ws[k][tx * 8 + 4];  // experts 4..7
            ull wr[4] = {wa.x, wa.y, wb.x, wb.y};
            float xr[8] = {xa.x, xa.y, xa.z, xa.w, xb.x, xb.y, xb.z, xb.w};
            #pragma unroll
            for (int i = 0; i < 8; i++) {
                ull xp;
                asm("mov.b64 %0, {%1, %1};" : "=l"(xp) : "r"(__float_as_uint(xr[i])));
                #pragma unroll
                for (int j = 0; j < 4; j++)
                    asm("fma.rn.f32x2 %0, %1, %2, %0;"
                        : "+l"(acc[i][j]) : "l"(xp), "l"(wr[j]));
            }
        }
        __syncthreads();
    }

    // Write split-K partials
    #pragma unroll
    for (int i = 0; i < 8; i++) {
        float o[8];
        #pragma unroll
        for (int j = 0; j < 4; j++) {
            unsigned lo, hi;
            asm("mov.b64 {%0, %1}, %2;" : "=r"(lo), "=r"(hi) : "l"(acc[i][j]));
            o[2 * j]     = __uint_as_float(lo);
            o[2 * j + 1] = __uint_as_float(hi);
        }
        float* dst = &g_part[ks][t0 + ty * 8 + i][tx * 8];
        *(float4*)(dst)     = make_float4(o[0], o[1], o[2], o[3]);
        *(float4*)(dst + 4) = make_float4(o[4], o[5], o[6], o[7]);
    }
}

// ---------------------------------------------------------------------------
// Gating: one thread per token. Sums split-K partials (fixed order), softmax,
// group-limited greedy top-6, normalized weights, aux-loss accumulators.
// All 64 scores live in registers (fully unrolled, constant indices).
// ---------------------------------------------------------------------------
__global__ __launch_bounds__(128) void gate_kernel(float* __restrict__ out) {
    const int tid = threadIdx.x;
    const int t   = blockIdx.x * 128 + tid;

    float sc[64];
    #pragma unroll
    for (int q = 0; q < 16; q++) {
        float4 v0 = *(const float4*)&g_part[0][t][q * 4];
        float4 v1 = *(const float4*)&g_part[1][t][q * 4];
        float4 v2 = *(const float4*)&g_part[2][t][q * 4];
        float4 v3 = *(const float4*)&g_part[3][t][q * 4];
        sc[q * 4 + 0] = ((v0.x + v1.x) + v2.x) + v3.x;
        sc[q * 4 + 1] = ((v0.y + v1.y) + v2.y) + v3.y;
        sc[q * 4 + 2] = ((v0.z + v1.z) + v2.z) + v3.z;
        sc[q * 4 + 3] = ((v0.w + v1.w) + v2.w) + v3.w;
    }

    // softmax over 64 logits
    float m = sc[0];
    #pragma unroll
    for (int e = 1; e < 64; e++) m = fmaxf(m, sc[e]);
    float s = 0.f;
    #pragma unroll
    for (int e = 0; e < 64; e++) { sc[e] = expf(sc[e] - m); s += sc[e]; }
    float inv = 1.0f / s;
    #pragma unroll
    for (int e = 0; e < 64; e++) sc[e] *= inv;

    // group maxima (8 groups of 8)
    float gm[8];
    #pragma unroll
    for (int g = 0; g < 8; g++) {
        float a = sc[g * 8];
        #pragma unroll
        for (int j = 1; j < 8; j++) a = fmaxf(a, sc[g * 8 + j]);
        gm[g] = a;
    }

    // top-3 groups (ties -> smallest index, matching lax.top_k)
    unsigned keep = 0;
    #pragma unroll
    for (int r = 0; r < 3; r++) {
        float bv = -1.f; int bi = 0;
        #pragma unroll
        for (int g = 0; g < 8; g++) {
            bool ok = !((keep >> g) & 1) && (gm[g] > bv);
            if (ok) { bv = gm[g]; bi = g; }
        }
        keep |= 1u << bi;
    }

    // top-6 experts within kept groups
    ull picked = 0;
    float wsum = 0.f;
    int idxs[6]; float vals[6];
    #pragma unroll
    for (int r = 0; r < 6; r++) {
        float bv = -1.f; int bi = 0;
        #pragma unroll
        for (int e = 0; e < 64; e++) {
            bool ok = ((keep >> (e >> 3)) & 1) && !((picked >> e) & 1) && (sc[e] > bv);
            if (ok) { bv = sc[e]; bi = e; }
        }
        picked |= 1ull << bi;
        idxs[r] = bi; vals[r] = bv; wsum += bv;
    }
    float inv2 = 1.0f / (wsum + 1e-20f);

    // outputs: [topk_idx (T*6) | topk_weight (T*6) | aux_loss (1)]
    #pragma unroll
    for (int r = 0; r < 6; r++) {
        out[t * TOPK + r]                  = (float)idxs[r];
        out[T_TOK * TOPK + t * TOPK + r]   = vals[r] * inv2;
    }

    // aux-loss accumulators: deterministic smem column reduction for score sums
    __shared__ float scs[128][65];
    __shared__ float scnt[64];
    if (tid < 64) scnt[tid] = 0.f;
    #pragma unroll
    for (int e = 0; e < 64; e++) scs[tid][e] = sc[e];
    __syncthreads();
    #pragma unroll
    for (int r = 0; r < 6; r++) atomicAdd(&scnt[idxs[r]], 1.0f);
    __syncthreads();
    if (tid < 64) {
        float a = 0.f;
        for (int i = 0; i < 128; i++) a += scs[i][tid];
        int b = (blockIdx.x * 128) / S_SEQ;   // 128-token blocks never straddle batches
        atomicAdd(&g_ssum[b][tid], a);
        atomicAdd(&g_cnt [b][tid], scnt[tid]);
    }
}

// aux_loss = ALPHA * mean_b sum_e (cnt/(S*K/E)) * (ssum/S)
__global__ void aux_kernel(float* __restrict__ out) {
    __shared__ float red[256];
    int tid = threadIdx.x;
    float a = ((const float*)g_cnt)[tid] * ((const float*)g_ssum)[tid];
    red[tid] = a;
    __syncthreads();
    for (int s2 = 128; s2 > 0; s2 >>= 1) {
        if (tid < s2) red[tid] += red[tid + s2];
        __syncthreads();
    }
    if (tid == 0)
        out[2 * T_TOK * TOPK] = red[0] * (0.001f / (4.0f * 384.0f * 4096.0f));
}

extern "C" void kernel_launch(void* const* d_in, const int* in_sizes, int n_in,
                              void* d_out, int out_size) {
    const float* X = (const float*)d_in[0];   // hidden_states [4,4096,4096] fp32
    const float* W = (const float*)d_in[1];   // weight [64,4096] fp32
    float* out = (float*)d_out;

    zero_kernel<<<1, 256>>>();
    dim3 grid(T_TOK / BM, KSPLIT);
    gemm_kernel<<<grid, 128>>>(X, W);
    gate_kernel<<<T_TOK / 128, 128>>>(out);
    aux_kernel<<<1, 256>>>(out);
}

// round 3
// speedup vs baseline: 2.4629x; 2.4629x over previous
#include <cuda_runtime.h>
#include <cuda_fp16.h>
#include <cstdint>

typedef unsigned long long ull;

constexpr int T_TOK = 16384;
constexpr int H_DIM = 4096;
constexpr int N_E   = 64;
constexpr int TOPK  = 6;
constexpr int S_SEQ = 4096;

constexpr int BM     = 128;           // tokens per CTA
constexpr int BK     = 64;            // fp32 K per stage
constexpr int NSTAGE = H_DIM / BK;    // 64
constexpr int NT     = 256;           // threads per CTA

constexpr int XBYTES = BM * BK * 4;       // 32768
constexpr int WBYTES = N_E * BK * 2 * 2;  // 16384 (2 splits, f16)
constexpr int STAGE  = XBYTES + WBYTES;   // 49152
constexpr int DYN    = 2 * STAGE;         // 98304

// static device scratch
__device__ __half g_W1[N_E * H_DIM];
__device__ __half g_W2[N_E * H_DIM];
__device__ float  g_ssum[4][64];
__device__ float  g_cnt [4][64];

// ---------------------------------------------------------------------------
__device__ __forceinline__ uint32_t smem_u32(const void* p) {
    return (uint32_t)__cvta_generic_to_shared(p);
}
__device__ __forceinline__ void cp16(uint32_t dst, const void* src) {
    asm volatile("cp.async.cg.shared.global [%0], [%1], 16;" :: "r"(dst), "l"(src));
}
__device__ __forceinline__ void ldsm4(uint32_t& r0, uint32_t& r1, uint32_t& r2,
                                      uint32_t& r3, uint32_t a) {
    asm volatile("ldmatrix.sync.aligned.m8n8.x4.shared.b16 {%0,%1,%2,%3}, [%4];"
                 : "=r"(r0), "=r"(r1), "=r"(r2), "=r"(r3) : "r"(a));
}
__device__ __forceinline__ void mma16816(float* c, const uint32_t* a,
                                         uint32_t b0, uint32_t b1) {
    asm volatile(
        "mma.sync.aligned.m16n8k16.row.col.f32.f16.f16.f32 "
        "{%0,%1,%2,%3}, {%4,%5,%6,%7}, {%8,%9}, {%0,%1,%2,%3};"
        : "+f"(c[0]), "+f"(c[1]), "+f"(c[2]), "+f"(c[3])
        : "r"(a[0]), "r"(a[1]), "r"(a[2]), "r"(a[3]), "r"(b0), "r"(b1));
}
// split a float2 (scaled by 32) into hi/lo f16 pairs
__device__ __forceinline__ void split32(float2 v, uint32_t& hi, uint32_t& lo) {
    v.x *= 32.f; v.y *= 32.f;
    __half2 h = __float22half2_rn(v);
    float2 b = __half22float2(h);
    __half2 L = __float22half2_rn(make_float2(v.x - b.x, v.y - b.y));
    hi = *(uint32_t*)&h;
    lo = *(uint32_t*)&L;
}
// X smem: row r (0..127) x 64 floats, 16B-unit swizzled: u' = (u&8)|((u^(r&7))&7)
__device__ __forceinline__ float2 ldx(const float* xb, int r, int k) {
    int u  = k >> 2;
    int up = (u & 8) | ((u ^ (r & 7)) & 7);
    return *(const float2*)(xb + r * 64 + up * 4 + (k & 3));
}

// ---------------------------------------------------------------------------
// Prep: split W into 2 f16 terms (scaled by 1024), zero aux accumulators
// ---------------------------------------------------------------------------
__global__ __launch_bounds__(256) void prep_kernel(const float* __restrict__ W) {
    int idx = blockIdx.x * 256 + threadIdx.x;
    if (blockIdx.x == 0) {
        ((float*)g_ssum)[threadIdx.x] = 0.f;
        ((float*)g_cnt )[threadIdx.x] = 0.f;
    }
    #pragma unroll
    for (int r = 0; r < 4; r++) {
        int i = idx + r * 16384;              // float4 index, 65536 total
        float4 v = ((const float4*)W)[i];
        float a0 = v.x * 1024.f, a1 = v.y * 1024.f, a2 = v.z * 1024.f, a3 = v.w * 1024.f;
        __half2 h01 = __float22half2_rn(make_float2(a0, a1));
        __half2 h23 = __float22half2_rn(make_float2(a2, a3));
        float2 b01 = __half22float2(h01);
        float2 b23 = __half22float2(h23);
        __half2 l01 = __float22half2_rn(make_float2(a0 - b01.x, a1 - b01.y));
        __half2 l23 = __float22half2_rn(make_float2(a2 - b23.x, a3 - b23.y));
        uint2 hw, lw;
        hw.x = *(uint32_t*)&h01; hw.y = *(uint32_t*)&h23;
        lw.x = *(uint32_t*)&l01; lw.y = *(uint32_t*)&l23;
        ((uint2*)g_W1)[i] = hw;
        ((uint2*)g_W2)[i] = lw;
    }
}

// ---------------------------------------------------------------------------
// Fused GEMM (split-f16 mma.sync) + gating epilogue
// ---------------------------------------------------------------------------
__global__ __launch_bounds__(NT, 1) void moe_kernel(const float* __restrict__ X,
                                                    float* __restrict__ out) {
    extern __shared__ char dsm[];
    __shared__ float s_red[4][64];
    __shared__ float s_cnt[64];

    const int tid  = threadIdx.x;
    const int w    = tid >> 5;
    const int l    = tid & 31;
    const int tile = blockIdx.x;
    const float* Xt = X + (size_t)tile * BM * H_DIM;

    if (tid < 64) s_cnt[tid] = 0.f;

    // stage loader (cp.async)
    auto load_stage = [&](int s) {
        const int k0 = s * BK;
        const uint32_t xb = smem_u32(dsm) + (s & 1) * STAGE;
        const uint32_t wb = xb + XBYTES;
        #pragma unroll
        for (int i = 0; i < 8; i++) {
            int ch = tid + i * NT;
            int r = ch >> 4, u = ch & 15;
            int up = (u & 8) | ((u ^ (r & 7)) & 7);
            cp16(xb + r * 256 + up * 16, Xt + (size_t)r * H_DIM + k0 + u * 4);
        }
        #pragma unroll
        for (int i = 0; i < 4; i++) {
            int ch = tid + i * NT;
            int e = ch >> 4, u = ch & 15;
            int split = u >> 3, kk = u & 7;
            int up = (u & 8) | ((u ^ (e & 7)) & 7);
            const __half* src = (split ? g_W2 : g_W1) + e * H_DIM + k0 + kk * 8;
            cp16(wb + e * 256 + up * 16, src);
        }
        asm volatile("cp.async.commit_group;");
    };

    float acc[8][4];
    #pragma unroll
    for (int i = 0; i < 8; i++)
        #pragma unroll
        for (int j = 0; j < 4; j++) acc[i][j] = 0.f;

    // per-thread B-fragment address precompute (ldmatrix x4 over 2 expert blocks)
    const int t8     = l >> 3;                    // tile index 0..3
    const int e_base = (t8 >> 1) * 8 + (l & 7);   // expert row this lane addresses
    const int koff   = t8 & 1;                    // k8 sub-chunk
    const int c7     = e_base & 7;

    load_stage(0);

    for (int s = 0; s < NSTAGE; s++) {
        if (s + 1 < NSTAGE) {
            load_stage(s + 1);
            asm volatile("cp.async.wait_group 1;");
        } else {
            asm volatile("cp.async.wait_group 0;");
        }
        __syncthreads();

        const char* sb = dsm + (s & 1) * STAGE;
        const float* xb = (const float*)sb;
        const uint32_t wbe = smem_u32(sb + XBYTES) + e_base * 256;
        const int r0 = w * 16 + (l >> 2);
        const int r1 = r0 + 8;

        #pragma unroll
        for (int c16 = 0; c16 < 4; c16++) {
            const int kA = c16 * 16 + (l & 3) * 2;
            uint32_t ahi[4], alo[4];
            split32(ldx(xb, r0, kA),     ahi[0], alo[0]);
            split32(ldx(xb, r1, kA),     ahi[1], alo[1]);
            split32(ldx(xb, r0, kA + 8), ahi[2], alo[2]);
            split32(ldx(xb, r1, kA + 8), ahi[3], alo[3]);

            const int u0  = c16 * 2 + koff;
            const int uph = (u0 ^ c7) & 7;
            #pragma unroll
            for (int pe = 0; pe < 4; pe++) {
                uint32_t ah = wbe + pe * 4096 + uph * 16;  // split-hi units 0..7
                uint32_t bh0, bh1, bh2, bh3, bl0, bl1, bl2, bl3;
                ldsm4(bh0, bh1, bh2, bh3, ah);
                ldsm4(bl0, bl1, bl2, bl3, ah + 128);       // split-lo units 8..15
                mma16816(acc[2 * pe],     ahi, bh0, bh1);
                mma16816(acc[2 * pe],     ahi, bl0, bl1);
                mma16816(acc[2 * pe],     alo, bh0, bh1);
                mma16816(acc[2 * pe + 1], ahi, bh2, bh3);
                mma16816(acc[2 * pe + 1], ahi, bl2, bl3);
                mma16816(acc[2 * pe + 1], alo, bh2, bh3);
            }
        }
        __syncthreads();
    }

    // ---------------- epilogue: transpose scores to smem ----------------
    float* S = (float*)dsm;               // [128][65] stride-65, conflict-free reads
    {
        const int r0 = w * 16 + (l >> 2);
        const int c0 = (l & 3) * 2;
        constexpr float INV = 1.0f / 32768.0f;
        #pragma unroll
        for (int eb = 0; eb < 8; eb++) {
            S[r0 * 65 + eb * 8 + c0]           = acc[eb][0] * INV;
            S[r0 * 65 + eb * 8 + c0 + 1]       = acc[eb][1] * INV;
            S[(r0 + 8) * 65 + eb * 8 + c0]     = acc[eb][2] * INV;
            S[(r0 + 8) * 65 + eb * 8 + c0 + 1] = acc[eb][3] * INV;
        }
    }
    __syncthreads();

    if (tid < 128) {
        float sc[64];
        #pragma unroll
        for (int e = 0; e < 64; e++) sc[e] = S[tid * 65 + e];

        // softmax
        float m = sc[0];
        #pragma unroll
        for (int e = 1; e < 64; e++) m = fmaxf(m, sc[e]);
        float ssum = 0.f;
        #pragma unroll
        for (int e = 0; e < 64; e++) { sc[e] = expf(sc[e] - m); ssum += sc[e]; }
        float inv = 1.0f / ssum;
        #pragma unroll
        for (int e = 0; e < 64; e++) sc[e] *= inv;

        // group maxima
        float gm[8];
        #pragma unroll
        for (int g = 0; g < 8; g++) {
            float a = sc[g * 8];
            #pragma unroll
            for (int j = 1; j < 8; j++) a = fmaxf(a, sc[g * 8 + j]);
            gm[g] = a;
        }
        // top-3 groups
        unsigned keep = 0;
        #pragma unroll
        for (int r = 0; r < 3; r++) {
            float bv = -1.f; int bi = 0;
            #pragma unroll
            for (int g = 0; g < 8; g++) {
                bool ok = !((keep >> g) & 1) && (gm[g] > bv);
                if (ok) { bv = gm[g]; bi = g; }
            }
            keep |= 1u << bi;
        }
        // top-6 experts in kept groups
        ull picked = 0;
        float wsum = 0.f;
        int idxs[6]; float vals[6];
        #pragma unroll
        for (int r = 0; r < 6; r++) {
            float bv = -1.f; int bi = 0;
            #pragma unroll
            for (int e = 0; e < 64; e++) {
                bool ok = ((keep >> (e >> 3)) & 1) && !((picked >> e) & 1) && (sc[e] > bv);
                if (ok) { bv = sc[e]; bi = e; }
            }
            picked |= 1ull << bi;
            idxs[r] = bi; vals[r] = bv; wsum += bv;
        }
        float inv2 = 1.0f / (wsum + 1e-20f);

        const int t = tile * BM + tid;
        #pragma unroll
        for (int r = 0; r < 6; r++) {
            out[t * TOPK + r]                = (float)idxs[r];
            out[T_TOK * TOPK + t * TOPK + r] = vals[r] * inv2;
        }

        // aux accumulators
        #pragma unroll
        for (int e = 0; e < 64; e++) {
            float v = sc[e];
            v += __shfl_xor_sync(0xffffffffu, v, 16);
            v += __shfl_xor_sync(0xffffffffu, v, 8);
            v += __shfl_xor_sync(0xffffffffu, v, 4);
            v += __shfl_xor_sync(0xffffffffu, v, 2);
            v += __shfl_xor_sync(0xffffffffu, v, 1);
            if (l == 0) s_red[w][e] = v;
        }
        #pragma unroll
        for (int r = 0; r < 6; r++) atomicAdd(&s_cnt[idxs[r]], 1.0f);
    }
    __syncthreads();
    if (tid < 64) {
        float a = s_red[0][tid] + s_red[1][tid] + s_red[2][tid] + s_red[3][tid];
        int b = (tile * BM) / S_SEQ;
        atomicAdd(&g_ssum[b][tid], a);
        atomicAdd(&g_cnt [b][tid], s_cnt[tid]);
    }
}

// aux_loss = ALPHA * mean_b sum_e (cnt/(S*K/E)) * (ssum/S)
__global__ void aux_kernel(float* __restrict__ out) {
    __shared__ float red[256];
    int tid = threadIdx.x;
    red[tid] = ((const float*)g_cnt)[tid] * ((const float*)g_ssum)[tid];
    __syncthreads();
    for (int s2 = 128; s2 > 0; s2 >>= 1) {
        if (tid < s2) red[tid] += red[tid + s2];
        __syncthreads();
    }
    if (tid == 0)
        out[2 * T_TOK * TOPK] = red[0] * (0.001f / (4.0f * 384.0f * 4096.0f));
}

extern "C" void kernel_launch(void* const* d_in, const int* in_sizes, int n_in,
                              void* d_out, int out_size) {
    const float* X = (const float*)d_in[0];   // [4,4096,4096] fp32
    const float* W = (const float*)d_in[1];   // [64,4096] fp32
    float* out = (float*)d_out;

    cudaFuncSetAttribute(moe_kernel, cudaFuncAttributeMaxDynamicSharedMemorySize, DYN);
    prep_kernel<<<64, 256>>>(W);
    moe_kernel<<<T_TOK / BM, NT, DYN>>>(X, out);
    aux_kernel<<<1, 256>>>(out);
}